// round 1
// baseline (speedup 1.0000x reference)
#include <cuda_runtime.h>
#include <math.h>

#define DIMD   384
#define INNERD 1536
#define NTOK   4096
#define NEXP   5
#define KSZ    31
#define TLEN   1024
#define NB     4

// ---------------- scratch (device globals; no allocation allowed) ----------------
__device__ float g_x  [NTOK*DIMD];            // layernorm output
__device__ float g_h  [NTOK*DIMD];            // conv output (tok)
__device__ float g_r1 [NTOK*DIMD];            // router hidden
__device__ float g_y  [NTOK*DIMD];            // tok + weighted expert out
__device__ float g_raw[(size_t)NTOK*2*INNERD];// pre-swiglu activations (reused)
__device__ float g_h1 [(size_t)NTOK*INNERD];
__device__ float g_h2 [(size_t)NTOK*INNERD];
__device__ int   g_cnt[NEXP];
__device__ int   g_idx[NEXP*NTOK];
__device__ float g_gw [NEXP*NTOK];
__device__ float g_pp [NB*8*DIMD];
__device__ float g_gate[NB*DIMD];

__device__ __forceinline__ float warp_sum(float v){
#pragma unroll
    for (int o = 16; o; o >>= 1) v += __shfl_xor_sync(0xffffffffu, v, o);
    return v;
}
__device__ __forceinline__ float siluf(float x){ return x / (1.f + expf(-x)); }

// ---------------- LayerNorm: res -> g_x ----------------
__global__ void ln_k(const float* __restrict__ res, const float* __restrict__ gg,
                     const float* __restrict__ bb){
    int n = blockIdx.x, tid = threadIdx.x;          // 128 threads, 3 elems each
    const float* r = res + (size_t)n*DIMD;
    float v0 = r[tid], v1 = r[tid+128], v2 = r[tid+256];
    __shared__ float redA[4], redB[4];
    int lane = tid & 31, wid = tid >> 5;
    float s = warp_sum(v0 + v1 + v2);
    if (lane == 0) redA[wid] = s;
    __syncthreads();
    float mu = (redA[0]+redA[1]+redA[2]+redA[3]) * (1.f/DIMD);
    float d0 = v0-mu, d1 = v1-mu, d2 = v2-mu;
    float q = warp_sum(d0*d0 + d1*d1 + d2*d2);
    if (lane == 0) redB[wid] = q;
    __syncthreads();
    float var = (redB[0]+redB[1]+redB[2]+redB[3]) * (1.f/DIMD);
    float inv = rsqrtf(var + 1e-5f);
    float* o = g_x + (size_t)n*DIMD;
    o[tid]     = d0*inv*gg[tid]     + bb[tid];
    o[tid+128] = d1*inv*gg[tid+128] + bb[tid+128];
    o[tid+256] = d2*inv*gg[tid+256] + bb[tid+256];
}

// ---------------- depthwise conv over T: g_x -> g_h (and y init) ----------------
__global__ void conv_k(const float* __restrict__ cw, const float* __restrict__ cb){
    int n = blockIdx.x, d = threadIdx.x;            // 384 threads = one token row
    int b = n >> 10, t = n & 1023;
    float acc = cb[d];
    const float* wrow = cw + d*KSZ;
#pragma unroll
    for (int j = 0; j < KSZ; j++){
        int tt = t + j - 15;
        if (tt >= 0 && tt < TLEN)
            acc += g_x[((size_t)(b*TLEN + tt))*DIMD + d] * wrow[j];
    }
    g_h[(size_t)n*DIMD + d] = acc;
    g_y[(size_t)n*DIMD + d] = acc;                  // y starts as tok
}

// ---------------- generic fp32 GEMM: C = act(A@W + bias) ----------------
// AMODE: 0 = dense(M rows), 1 = gather rows via g_idx (guard by cnt),
//        2 = dense-compacted rows, guard by cnt
// SILU: apply silu elementwise. SCATTER: y[idx[row]] += gw[row]*val instead of store.
#define BM 64
#define BN 64
#define BK 16
template<int AMODE, int SILU, int SCATTER>
__global__ __launch_bounds__(256) void gemm_k(
    const float* __restrict__ A, const float* __restrict__ W,
    const float* __restrict__ bias, float* __restrict__ C,
    int M, int Nn, int K, int e, float* __restrict__ Y)
{
    int Mg = (AMODE == 0) ? M : g_cnt[e];
    int bm = blockIdx.y * BM, bn = blockIdx.x * BN;
    if (AMODE != 0 && bm >= Mg) return;             // skip fully-inactive tiles

    __shared__ float As[BK][BM + 4];
    __shared__ float Bs[BK][BN];
    int tid = threadIdx.x;
    int arow = tid >> 2,  ak = (tid & 3)  << 2;     // A: 64 rows x 16 k
    int brow = tid >> 4,  bc = (tid & 15) << 2;     // B: 16 k   x 64 n
    int ty = tid >> 4,    tx = tid & 15;

    int gr = bm + arow;
    bool aval = true;
    const float* Ap;
    if (AMODE == 1){ aval = gr < Mg; Ap = A + (aval ? (size_t)g_idx[e*NTOK + gr]*K : 0); }
    else if (AMODE == 2){ aval = gr < Mg; Ap = A + (size_t)gr*K; }
    else { Ap = A + (size_t)gr*K; }
    const float* Wp = W + (size_t)brow*Nn + bn + bc;

    float acc[4][4] = {};
    for (int kt = 0; kt < K; kt += BK){
        float4 av = aval ? *(const float4*)(Ap + kt + ak) : make_float4(0.f,0.f,0.f,0.f);
        As[ak+0][arow] = av.x; As[ak+1][arow] = av.y;
        As[ak+2][arow] = av.z; As[ak+3][arow] = av.w;
        *(float4*)&Bs[brow][bc] = *(const float4*)(Wp + (size_t)kt*Nn);
        __syncthreads();
#pragma unroll
        for (int kk = 0; kk < BK; kk++){
            float4 a = *(const float4*)&As[kk][ty << 2];
            float4 b = *(const float4*)&Bs[kk][tx << 2];
            acc[0][0] += a.x*b.x; acc[0][1] += a.x*b.y; acc[0][2] += a.x*b.z; acc[0][3] += a.x*b.w;
            acc[1][0] += a.y*b.x; acc[1][1] += a.y*b.y; acc[1][2] += a.y*b.z; acc[1][3] += a.y*b.w;
            acc[2][0] += a.z*b.x; acc[2][1] += a.z*b.y; acc[2][2] += a.z*b.z; acc[2][3] += a.z*b.w;
            acc[3][0] += a.w*b.x; acc[3][1] += a.w*b.y; acc[3][2] += a.w*b.z; acc[3][3] += a.w*b.w;
        }
        __syncthreads();
    }
#pragma unroll
    for (int i = 0; i < 4; i++){
        int rg = bm + (ty << 2) + i;
        if (AMODE != 0 && rg >= Mg) continue;
        int tn = 0; float wt = 0.f;
        if (SCATTER){ tn = g_idx[e*NTOK + rg]; wt = g_gw[e*NTOK + rg]; }
#pragma unroll
        for (int j = 0; j < 4; j++){
            int cg = bn + (tx << 2) + j;
            float v = acc[i][j] + bias[cg];
            if (SILU) v = siluf(v);
            if (SCATTER) Y[(size_t)tn*Nn + cg] += wt * v;   // unique (tn,cg) per launch
            else         C[(size_t)rg*Nn + cg] = v;
        }
    }
}

// ---------------- router logits + top-2 + softmax + gather-list build ----------------
__global__ void zero_k(){ if (threadIdx.x < NEXP) g_cnt[threadIdx.x] = 0; }

__global__ void route_k(const float* __restrict__ rw2, const float* __restrict__ rb2){
    int gt = blockIdx.x*blockDim.x + threadIdx.x;
    int n = gt >> 5, lane = gt & 31;
    if (n >= NTOK) return;
    const float* row = g_r1 + (size_t)n*DIMD;
    float a0=0,a1=0,a2=0,a3=0,a4=0;
    for (int d = lane; d < DIMD; d += 32){
        float v = row[d];
        const float* w = rw2 + d*NEXP;
        a0 += v*w[0]; a1 += v*w[1]; a2 += v*w[2]; a3 += v*w[3]; a4 += v*w[4];
    }
    a0=warp_sum(a0); a1=warp_sum(a1); a2=warp_sum(a2); a3=warp_sum(a3); a4=warp_sum(a4);
    if (lane == 0){
        float v[NEXP] = {a0+rb2[0], a1+rb2[1], a2+rb2[2], a3+rb2[3], a4+rb2[4]};
        int e0 = 0;
        for (int e = 1; e < NEXP; e++) if (v[e] > v[e0]) e0 = e;       // first max
        int e1 = -1;
        for (int e = 0; e < NEXP; e++){ if (e == e0) continue; if (e1 < 0 || v[e] > v[e1]) e1 = e; }
        float ex = expf(v[e1] - v[e0]);                                // softmax over {e0,e1}
        float w0 = 1.f/(1.f+ex), w1 = ex/(1.f+ex);
        int p0 = atomicAdd(&g_cnt[e0], 1); g_idx[e0*NTOK+p0] = n; g_gw[e0*NTOK+p0] = w0;
        int p1 = atomicAdd(&g_cnt[e1], 1); g_idx[e1*NTOK+p1] = n; g_gw[e1*NTOK+p1] = w1;
    }
}

// ---------------- swiglu: raw[.,2I] -> out[.,I] (guarded by cnt) ----------------
__global__ void swiglu_k(const float* __restrict__ raw, float* __restrict__ o, int e){
    int i = blockIdx.y;
    if (i >= g_cnt[e]) return;
    int c = blockIdx.x*256 + threadIdx.x;
    float a = raw[(size_t)i*(2*INNERD) + c];
    float g = raw[(size_t)i*(2*INNERD) + INNERD + c];
    o[(size_t)i*INNERD + c] = a * siluf(g);
}

// ---------------- senet pooled partials: (x*senet + y) summed over T-chunks ----------------
__global__ void pool_k(const float* __restrict__ senet){
    int tc = blockIdx.x, dc = blockIdx.y, b = blockIdx.z, tid = threadIdx.x;
    int d = dc*128 + tid;
    float sr = senet[d];
    float acc = 0.f;
    int base = b*TLEN + tc*128;
    for (int t = 0; t < 128; t++){
        size_t nn = (size_t)(base + t)*DIMD + d;
        acc += g_x[nn]*sr + g_y[nn];
    }
    g_pp[(b*8 + tc)*DIMD + d] = acc;
}

// ---------------- senet gate MLP (tiny): pooled -> sigmoid gate ----------------
__global__ void gate_k(const float* __restrict__ sw1, const float* __restrict__ sb1,
                       const float* __restrict__ sw2, const float* __restrict__ sb2){
    int b = blockIdx.x, tid = threadIdx.x;          // 384 threads
    __shared__ float pooled[DIMD];
    __shared__ float s1[48];
    float s = 0.f;
    for (int ch = 0; ch < 8; ch++) s += g_pp[(b*8 + ch)*DIMD + tid];
    pooled[tid] = s * (1.f/1024.f);
    __syncthreads();
    if (tid < 48){
        float acc = sb1[tid];
        for (int d = 0; d < DIMD; d++) acc += pooled[d]*sw1[d*48 + tid];
        s1[tid] = siluf(acc);
    }
    __syncthreads();
    float acc = sb2[tid];
    for (int q = 0; q < 48; q++) acc += s1[q]*sw2[q*DIMD + tid];
    g_gate[b*DIMD + tid] = 1.f/(1.f + expf(-acc));
}

// ---------------- final: out = res + y*gate ----------------
__global__ void final_k(const float* __restrict__ res, float* __restrict__ out){
    int i = blockIdx.x*256 + threadIdx.x;
    if (i >= NTOK*DIMD) return;
    int d = i % DIMD;
    int b = i / (TLEN*DIMD);
    out[i] = res[i] + g_y[i]*g_gate[b*DIMD + d];
}

// =============================== launch ===============================
extern "C" void kernel_launch(void* const* d_in, const int* in_sizes, int n_in,
                              void* d_out, int out_size){
    const float* res    = (const float*)d_in[0];
    const float* ln_g   = (const float*)d_in[1];
    const float* ln_b   = (const float*)d_in[2];
    const float* conv_w = (const float*)d_in[3];
    const float* conv_b = (const float*)d_in[4];
    const float* rw1    = (const float*)d_in[5];
    const float* rb1    = (const float*)d_in[6];
    const float* rw2    = (const float*)d_in[7];
    const float* rb2    = (const float*)d_in[8];
    const float* we1    = (const float*)d_in[9];
    const float* be1    = (const float*)d_in[10];
    const float* we2    = (const float*)d_in[11];
    const float* be2    = (const float*)d_in[12];
    const float* we3    = (const float*)d_in[13];
    const float* be3    = (const float*)d_in[14];
    const float* sw1    = (const float*)d_in[15];
    const float* sb1    = (const float*)d_in[16];
    const float* sw2    = (const float*)d_in[17];
    const float* sb2    = (const float*)d_in[18];
    const float* senet  = (const float*)d_in[19];
    float* out = (float*)d_out;

    float *ph, *pr1, *praw, *ph1, *ph2, *py;
    cudaGetSymbolAddress((void**)&ph,   g_h);
    cudaGetSymbolAddress((void**)&pr1,  g_r1);
    cudaGetSymbolAddress((void**)&praw, g_raw);
    cudaGetSymbolAddress((void**)&ph1,  g_h1);
    cudaGetSymbolAddress((void**)&ph2,  g_h2);
    cudaGetSymbolAddress((void**)&py,   g_y);

    ln_k  <<<NTOK, 128>>>(res, ln_g, ln_b);
    conv_k<<<NTOK, DIMD>>>(conv_w, conv_b);

    // router hidden: r1 = silu(h @ rw1 + rb1)   [4096,384]
    gemm_k<0,1,0><<<dim3(DIMD/BN, NTOK/BM), 256>>>(ph, rw1, rb1, pr1,
                                                   NTOK, DIMD, DIMD, 0, nullptr);
    zero_k <<<1, 32>>>();
    route_k<<<NTOK/8, 256>>>(rw2, rb2);

    for (int e = 0; e < NEXP; e++){
        const float* w1 = we1 + (size_t)e*DIMD*2*INNERD;
        const float* b1 = be1 + (size_t)e*2*INNERD;
        const float* w2 = we2 + (size_t)e*INNERD*2*INNERD;
        const float* b2 = be2 + (size_t)e*2*INNERD;
        const float* w3 = we3 + (size_t)e*INNERD*DIMD;
        const float* b3 = be3 + (size_t)e*DIMD;
        // L1: gathered tokens @ we1 -> raw [cnt,3072]
        gemm_k<1,0,0><<<dim3(2*INNERD/BN, NTOK/BM), 256>>>(ph, w1, b1, praw,
                                                           NTOK, 2*INNERD, DIMD, e, nullptr);
        swiglu_k<<<dim3(INNERD/256, NTOK), 256>>>(praw, ph1, e);
        // L2: h1 @ we2 -> raw [cnt,3072]
        gemm_k<2,0,0><<<dim3(2*INNERD/BN, NTOK/BM), 256>>>(ph1, w2, b2, praw,
                                                           NTOK, 2*INNERD, INNERD, e, nullptr);
        swiglu_k<<<dim3(INNERD/256, NTOK), 256>>>(praw, ph2, e);
        // L3: h2 @ we3, scatter-accumulate w * eo into y
        gemm_k<2,0,1><<<dim3(DIMD/BN, NTOK/BM), 256>>>(ph2, w3, b3, nullptr,
                                                       NTOK, DIMD, INNERD, e, py);
    }

    pool_k <<<dim3(8, 3, NB), 128>>>(senet);
    gate_k <<<NB, DIMD>>>(sw1, sb1, sw2, sb2);
    final_k<<<(NTOK*DIMD + 255)/256, 256>>>(res, out);
}

// round 2
// speedup vs baseline: 2.1811x; 2.1811x over previous
#include <cuda_runtime.h>
#include <math.h>
#include <stdint.h>

#define DIMD   384
#define INNERD 1536
#define NTOK   4096
#define NEXP   5
#define KSZ    31
#define TLEN   1024
#define NB     4

// ---------------- scratch (device globals) ----------------
__device__ float g_x  [NTOK*DIMD];
__device__ float g_h  [NTOK*DIMD];
__device__ float g_r1 [NTOK*DIMD];
__device__ float g_y  [NTOK*DIMD];
__device__ float g_h1 [(size_t)NTOK*INNERD];
__device__ float g_h2 [(size_t)NTOK*INNERD];
__device__ int   g_cnt[NEXP];
__device__ int   g_idx[NEXP*NTOK];
__device__ float g_gw [NEXP*NTOK];
__device__ float g_pp [NB*8*DIMD];
__device__ float g_gate[NB*DIMD];

__device__ __forceinline__ float warp_sum(float v){
#pragma unroll
    for (int o = 16; o; o >>= 1) v += __shfl_xor_sync(0xffffffffu, v, o);
    return v;
}
__device__ __forceinline__ float siluf(float x){ return x / (1.f + expf(-x)); }
__device__ __forceinline__ uint32_t f2tf32(float v){
    uint32_t o; asm("cvt.rna.tf32.f32 %0, %1;" : "=r"(o) : "f"(v)); return o;
}

#define MMA_TF32(c0,c1,c2,c3,a0,a1,a2,a3,b0,b1) \
    asm volatile("mma.sync.aligned.m16n8k8.row.col.f32.tf32.tf32.f32 " \
        "{%0,%1,%2,%3}, {%4,%5,%6,%7}, {%8,%9}, {%0,%1,%2,%3};" \
        : "+f"(c0),"+f"(c1),"+f"(c2),"+f"(c3) \
        : "r"(a0),"r"(a1),"r"(a2),"r"(a3),"r"(b0),"r"(b1))

// ---------------- LayerNorm ----------------
__global__ void ln_k(const float* __restrict__ res, const float* __restrict__ gg,
                     const float* __restrict__ bb){
    int n = blockIdx.x, tid = threadIdx.x;
    const float* r = res + (size_t)n*DIMD;
    float v0 = r[tid], v1 = r[tid+128], v2 = r[tid+256];
    __shared__ float redA[4], redB[4];
    int lane = tid & 31, wid = tid >> 5;
    float s = warp_sum(v0 + v1 + v2);
    if (lane == 0) redA[wid] = s;
    __syncthreads();
    float mu = (redA[0]+redA[1]+redA[2]+redA[3]) * (1.f/DIMD);
    float d0 = v0-mu, d1 = v1-mu, d2 = v2-mu;
    float q = warp_sum(d0*d0 + d1*d1 + d2*d2);
    if (lane == 0) redB[wid] = q;
    __syncthreads();
    float var = (redB[0]+redB[1]+redB[2]+redB[3]) * (1.f/DIMD);
    float inv = rsqrtf(var + 1e-5f);
    float* o = g_x + (size_t)n*DIMD;
    o[tid]     = d0*inv*gg[tid]     + bb[tid];
    o[tid+128] = d1*inv*gg[tid+128] + bb[tid+128];
    o[tid+256] = d2*inv*gg[tid+256] + bb[tid+256];
}

// ---------------- depthwise conv ----------------
__global__ void conv_k(const float* __restrict__ cw, const float* __restrict__ cb){
    int n = blockIdx.x, d = threadIdx.x;
    int b = n >> 10, t = n & 1023;
    float acc = cb[d];
    const float* wrow = cw + d*KSZ;
#pragma unroll
    for (int j = 0; j < KSZ; j++){
        int tt = t + j - 15;
        if (tt >= 0 && tt < TLEN)
            acc += g_x[((size_t)(b*TLEN + tt))*DIMD + d] * wrow[j];
    }
    g_h[(size_t)n*DIMD + d] = acc;
    g_y[(size_t)n*DIMD + d] = acc;
}

// ---------------- fp32 SIMT GEMM (router only, exact routing) ----------------
#define BMr 64
#define BNr 64
#define BKr 16
__global__ __launch_bounds__(256) void gemm_r_k(
    const float* __restrict__ A, const float* __restrict__ W,
    const float* __restrict__ bias, float* __restrict__ C,
    int M, int Nn, int K)
{
    int bm = blockIdx.y * BMr, bn = blockIdx.x * BNr;
    __shared__ float As[BKr][BMr + 4];
    __shared__ float Bs[BKr][BNr];
    int tid = threadIdx.x;
    int arow = tid >> 2,  ak = (tid & 3)  << 2;
    int brow = tid >> 4,  bc = (tid & 15) << 2;
    int ty = tid >> 4,    tx = tid & 15;
    const float* Ap = A + (size_t)(bm + arow)*K;
    const float* Wp = W + (size_t)brow*Nn + bn + bc;
    float acc[4][4] = {};
    for (int kt = 0; kt < K; kt += BKr){
        float4 av = *(const float4*)(Ap + kt + ak);
        As[ak+0][arow] = av.x; As[ak+1][arow] = av.y;
        As[ak+2][arow] = av.z; As[ak+3][arow] = av.w;
        *(float4*)&Bs[brow][bc] = *(const float4*)(Wp + (size_t)kt*Nn);
        __syncthreads();
#pragma unroll
        for (int kk = 0; kk < BKr; kk++){
            float4 a = *(const float4*)&As[kk][ty << 2];
            float4 b = *(const float4*)&Bs[kk][tx << 2];
            acc[0][0] += a.x*b.x; acc[0][1] += a.x*b.y; acc[0][2] += a.x*b.z; acc[0][3] += a.x*b.w;
            acc[1][0] += a.y*b.x; acc[1][1] += a.y*b.y; acc[1][2] += a.y*b.z; acc[1][3] += a.y*b.w;
            acc[2][0] += a.z*b.x; acc[2][1] += a.z*b.y; acc[2][2] += a.z*b.z; acc[2][3] += a.z*b.w;
            acc[3][0] += a.w*b.x; acc[3][1] += a.w*b.y; acc[3][2] += a.w*b.z; acc[3][3] += a.w*b.w;
        }
        __syncthreads();
    }
#pragma unroll
    for (int i = 0; i < 4; i++){
#pragma unroll
        for (int j = 0; j < 4; j++){
            int cg = bn + (tx << 2) + j;
            float v = acc[i][j] + bias[cg];
            C[(size_t)(bm + (ty<<2) + i)*Nn + cg] = siluf(v);
        }
    }
}

// ---------------- tf32 tensor-core GEMM for experts ----------------
// AMODE: 1 = gather A rows via g_idx, 2 = dense-compacted rows
// EPI:   2 = fused swiglu store (B holds both halves), 3 = scatter y += gw*(acc+bias)
#define BM 128
#define BK 32
template<int AMODE, int EPI>
__global__ __launch_bounds__(256) void tgemm_k(
    const float* __restrict__ A, const float* __restrict__ W,
    const float* __restrict__ bias, float* __restrict__ C,
    int K, int ldw, int nout, int e, float* __restrict__ Y)
{
    constexpr int BW = (EPI == 2) ? 128 : 64;   // B smem width (cols)
    constexpr int NH = (EPI == 2) ? 2 : 1;      // halves
    __shared__ uint32_t As[BM][BK + 4];
    __shared__ uint32_t Bs[BK][BW + 4];

    int cnt = g_cnt[e];
    int bm = blockIdx.y * BM;
    if (bm >= cnt) return;
    int bn = blockIdx.x * 64;

    int tid = threadIdx.x, lane = tid & 31, wid = tid >> 5;
    int wm = wid & 3, wn = wid >> 2;
    int g = lane >> 2, tg = lane & 3;

    // per-thread A source pointers (4 rows handled across iters)
    int arow = tid >> 3, ac4 = tid & 7;
    const float* aptr[4];
#pragma unroll
    for (int it = 0; it < 4; it++){
        int r = arow + it*32;
        int rg = bm + r;
        int srow = -1;
        if (rg < cnt) srow = (AMODE == 1) ? g_idx[e*NTOK + rg] : rg;
        aptr[it] = (srow >= 0) ? (A + (size_t)srow*K + ac4*4) : nullptr;
    }

    float acc[NH][2][4][4];
#pragma unroll
    for (int h = 0; h < NH; h++)
#pragma unroll
    for (int i = 0; i < 2; i++)
#pragma unroll
    for (int j = 0; j < 4; j++)
#pragma unroll
    for (int r = 0; r < 4; r++) acc[h][i][j][r] = 0.f;

    for (int kt = 0; kt < K; kt += BK){
        // ---- load A tile [BM x BK] ----
#pragma unroll
        for (int it = 0; it < 4; it++){
            int r = arow + it*32;
            float4 v = aptr[it] ? *(const float4*)(aptr[it] + kt)
                                : make_float4(0.f,0.f,0.f,0.f);
            As[r][ac4*4+0] = f2tf32(v.x); As[r][ac4*4+1] = f2tf32(v.y);
            As[r][ac4*4+2] = f2tf32(v.z); As[r][ac4*4+3] = f2tf32(v.w);
        }
        // ---- load B tile [BK x BW] ----
        if (EPI == 2){
            int br = tid >> 5, bc4 = tid & 31;
#pragma unroll
            for (int it = 0; it < 4; it++){
                int r = br + it*8;
                int col = (bc4 < 16) ? (bn + bc4*4) : (INNERD + bn + (bc4-16)*4);
                float4 v = *(const float4*)(W + (size_t)(kt + r)*ldw + col);
                Bs[r][bc4*4+0] = f2tf32(v.x); Bs[r][bc4*4+1] = f2tf32(v.y);
                Bs[r][bc4*4+2] = f2tf32(v.z); Bs[r][bc4*4+3] = f2tf32(v.w);
            }
        } else {
            int br = tid >> 4, bc4 = tid & 15;
#pragma unroll
            for (int it = 0; it < 2; it++){
                int r = br + it*16;
                float4 v = *(const float4*)(W + (size_t)(kt + r)*ldw + bn + bc4*4);
                Bs[r][bc4*4+0] = f2tf32(v.x); Bs[r][bc4*4+1] = f2tf32(v.y);
                Bs[r][bc4*4+2] = f2tf32(v.z); Bs[r][bc4*4+3] = f2tf32(v.w);
            }
        }
        __syncthreads();

#pragma unroll
        for (int kk = 0; kk < 4; kk++){
            uint32_t a[2][4];
#pragma unroll
            for (int i = 0; i < 2; i++){
                int r0 = wm*32 + i*16;
                a[i][0] = As[r0+g   ][kk*8+tg  ];
                a[i][1] = As[r0+g+8 ][kk*8+tg  ];
                a[i][2] = As[r0+g   ][kk*8+tg+4];
                a[i][3] = As[r0+g+8 ][kk*8+tg+4];
            }
#pragma unroll
            for (int h = 0; h < NH; h++){
#pragma unroll
                for (int j = 0; j < 4; j++){
                    int c0 = h*64 + wn*32 + j*8 + g;
                    uint32_t b0 = Bs[kk*8+tg  ][c0];
                    uint32_t b1 = Bs[kk*8+tg+4][c0];
#pragma unroll
                    for (int i = 0; i < 2; i++)
                        MMA_TF32(acc[h][i][j][0], acc[h][i][j][1],
                                 acc[h][i][j][2], acc[h][i][j][3],
                                 a[i][0], a[i][1], a[i][2], a[i][3], b0, b1);
                }
            }
        }
        __syncthreads();
    }

    // ---- epilogue ----
#pragma unroll
    for (int i = 0; i < 2; i++){
        int rA = bm + wm*32 + i*16 + g;
        int rB = rA + 8;
#pragma unroll
        for (int j = 0; j < 4; j++){
            int col = bn + wn*32 + j*8 + 2*tg;      // even col; odd = col+1
            if (EPI == 2){
                float ba0 = bias[col],          ba1 = bias[col+1];
                float bg0 = bias[INNERD+col],   bg1 = bias[INNERD+col+1];
                if (rA < cnt){
                    C[(size_t)rA*nout + col    ] = (acc[0][i][j][0]+ba0)*siluf(acc[1][i][j][0]+bg0);
                    C[(size_t)rA*nout + col + 1] = (acc[0][i][j][1]+ba1)*siluf(acc[1][i][j][1]+bg1);
                }
                if (rB < cnt){
                    C[(size_t)rB*nout + col    ] = (acc[0][i][j][2]+ba0)*siluf(acc[1][i][j][2]+bg0);
                    C[(size_t)rB*nout + col + 1] = (acc[0][i][j][3]+ba1)*siluf(acc[1][i][j][3]+bg1);
                }
            } else {
                float b0 = bias[col], b1 = bias[col+1];
                if (rA < cnt){
                    int tn = g_idx[e*NTOK + rA]; float wt = g_gw[e*NTOK + rA];
                    Y[(size_t)tn*nout + col    ] += wt*(acc[0][i][j][0] + b0);
                    Y[(size_t)tn*nout + col + 1] += wt*(acc[0][i][j][1] + b1);
                }
                if (rB < cnt){
                    int tn = g_idx[e*NTOK + rB]; float wt = g_gw[e*NTOK + rB];
                    Y[(size_t)tn*nout + col    ] += wt*(acc[0][i][j][2] + b0);
                    Y[(size_t)tn*nout + col + 1] += wt*(acc[0][i][j][3] + b1);
                }
            }
        }
    }
}

// ---------------- router top-2 ----------------
__global__ void zero_k(){ if (threadIdx.x < NEXP) g_cnt[threadIdx.x] = 0; }

__global__ void route_k(const float* __restrict__ rw2, const float* __restrict__ rb2){
    int gt = blockIdx.x*blockDim.x + threadIdx.x;
    int n = gt >> 5, lane = gt & 31;
    if (n >= NTOK) return;
    const float* row = g_r1 + (size_t)n*DIMD;
    float a0=0,a1=0,a2=0,a3=0,a4=0;
    for (int d = lane; d < DIMD; d += 32){
        float v = row[d];
        const float* w = rw2 + d*NEXP;
        a0 += v*w[0]; a1 += v*w[1]; a2 += v*w[2]; a3 += v*w[3]; a4 += v*w[4];
    }
    a0=warp_sum(a0); a1=warp_sum(a1); a2=warp_sum(a2); a3=warp_sum(a3); a4=warp_sum(a4);
    if (lane == 0){
        float v[NEXP] = {a0+rb2[0], a1+rb2[1], a2+rb2[2], a3+rb2[3], a4+rb2[4]};
        int e0 = 0;
        for (int e = 1; e < NEXP; e++) if (v[e] > v[e0]) e0 = e;
        int e1 = -1;
        for (int e = 0; e < NEXP; e++){ if (e == e0) continue; if (e1 < 0 || v[e] > v[e1]) e1 = e; }
        float ex = expf(v[e1] - v[e0]);
        float w0 = 1.f/(1.f+ex), w1 = ex/(1.f+ex);
        int p0 = atomicAdd(&g_cnt[e0], 1); g_idx[e0*NTOK+p0] = n; g_gw[e0*NTOK+p0] = w0;
        int p1 = atomicAdd(&g_cnt[e1], 1); g_idx[e1*NTOK+p1] = n; g_gw[e1*NTOK+p1] = w1;
    }
}

// ---------------- senet ----------------
__global__ void pool_k(const float* __restrict__ senet){
    int tc = blockIdx.x, dc = blockIdx.y, b = blockIdx.z, tid = threadIdx.x;
    int d = dc*128 + tid;
    float sr = senet[d];
    float acc = 0.f;
    int base = b*TLEN + tc*128;
    for (int t = 0; t < 128; t++){
        size_t nn = (size_t)(base + t)*DIMD + d;
        acc += g_x[nn]*sr + g_y[nn];
    }
    g_pp[(b*8 + tc)*DIMD + d] = acc;
}

__global__ void gate_k(const float* __restrict__ sw1, const float* __restrict__ sb1,
                       const float* __restrict__ sw2, const float* __restrict__ sb2){
    int b = blockIdx.x, tid = threadIdx.x;
    __shared__ float pooled[DIMD];
    __shared__ float s1[48];
    float s = 0.f;
    for (int ch = 0; ch < 8; ch++) s += g_pp[(b*8 + ch)*DIMD + tid];
    pooled[tid] = s * (1.f/1024.f);
    __syncthreads();
    if (tid < 48){
        float acc = sb1[tid];
        for (int d = 0; d < DIMD; d++) acc += pooled[d]*sw1[d*48 + tid];
        s1[tid] = siluf(acc);
    }
    __syncthreads();
    float acc = sb2[tid];
    for (int q = 0; q < 48; q++) acc += s1[q]*sw2[q*DIMD + tid];
    g_gate[b*DIMD + tid] = 1.f/(1.f + expf(-acc));
}

__global__ void final_k(const float* __restrict__ res, float* __restrict__ out){
    int i = blockIdx.x*256 + threadIdx.x;
    if (i >= NTOK*DIMD) return;
    int d = i % DIMD;
    int b = i / (TLEN*DIMD);
    out[i] = res[i] + g_y[i]*g_gate[b*DIMD + d];
}

// =============================== launch ===============================
extern "C" void kernel_launch(void* const* d_in, const int* in_sizes, int n_in,
                              void* d_out, int out_size){
    const float* res    = (const float*)d_in[0];
    const float* ln_g   = (const float*)d_in[1];
    const float* ln_b   = (const float*)d_in[2];
    const float* conv_w = (const float*)d_in[3];
    const float* conv_b = (const float*)d_in[4];
    const float* rw1    = (const float*)d_in[5];
    const float* rb1    = (const float*)d_in[6];
    const float* rw2    = (const float*)d_in[7];
    const float* rb2    = (const float*)d_in[8];
    const float* we1    = (const float*)d_in[9];
    const float* be1    = (const float*)d_in[10];
    const float* we2    = (const float*)d_in[11];
    const float* be2    = (const float*)d_in[12];
    const float* we3    = (const float*)d_in[13];
    const float* be3    = (const float*)d_in[14];
    const float* sw1    = (const float*)d_in[15];
    const float* sb1    = (const float*)d_in[16];
    const float* sw2    = (const float*)d_in[17];
    const float* sb2    = (const float*)d_in[18];
    const float* senet  = (const float*)d_in[19];
    float* out = (float*)d_out;

    float *ph, *pr1, *ph1, *ph2, *py;
    cudaGetSymbolAddress((void**)&ph,   g_h);
    cudaGetSymbolAddress((void**)&pr1,  g_r1);
    cudaGetSymbolAddress((void**)&ph1,  g_h1);
    cudaGetSymbolAddress((void**)&ph2,  g_h2);
    cudaGetSymbolAddress((void**)&py,   g_y);

    ln_k  <<<NTOK, 128>>>(res, ln_g, ln_b);
    conv_k<<<NTOK, DIMD>>>(conv_w, conv_b);

    // router hidden in exact fp32 (protect top-k selection)
    gemm_r_k<<<dim3(DIMD/BNr, NTOK/BMr), 256>>>(ph, rw1, rb1, pr1, NTOK, DIMD, DIMD);
    zero_k <<<1, 32>>>();
    route_k<<<NTOK/8, 256>>>(rw2, rb2);

    for (int e = 0; e < NEXP; e++){
        const float* w1 = we1 + (size_t)e*DIMD*2*INNERD;
        const float* b1 = be1 + (size_t)e*2*INNERD;
        const float* w2 = we2 + (size_t)e*INNERD*2*INNERD;
        const float* b2 = be2 + (size_t)e*2*INNERD;
        const float* w3 = we3 + (size_t)e*INNERD*DIMD;
        const float* b3 = be3 + (size_t)e*DIMD;
        // L1: gathered tokens -> swiglu -> h1  [cnt,1536]
        tgemm_k<1,2><<<dim3(INNERD/64, NTOK/BM), 256>>>(ph,  w1, b1, ph1,
                                                        DIMD,   2*INNERD, INNERD, e, nullptr);
        // L2: h1 -> swiglu -> h2  [cnt,1536]
        tgemm_k<2,2><<<dim3(INNERD/64, NTOK/BM), 256>>>(ph1, w2, b2, ph2,
                                                        INNERD, 2*INNERD, INNERD, e, nullptr);
        // L3: h2 @ we3 -> scatter y += gw*(out+bias)
        tgemm_k<2,3><<<dim3(DIMD/64,   NTOK/BM), 256>>>(ph2, w3, b3, nullptr,
                                                        INNERD, DIMD,     DIMD,   e, py);
    }

    pool_k <<<dim3(8, 3, NB), 128>>>(senet);
    gate_k <<<NB, DIMD>>>(sw1, sb1, sw2, sb2);
    final_k<<<(NTOK*DIMD + 255)/256, 256>>>(res, out);
}

// round 3
// speedup vs baseline: 5.5921x; 2.5639x over previous
#include <cuda_runtime.h>
#include <cuda_bf16.h>
#include <math.h>
#include <stdint.h>

#define DIMD   384
#define INNERD 1536
#define NTOK   4096
#define NEXP   5
#define KSZ    31
#define TLEN   1024
#define NB     4

// ---------------- scratch (device globals) ----------------
__device__ float g_x  [NTOK*DIMD];
__device__ float g_h  [NTOK*DIMD];                 // conv out fp32 (router, combine)
__device__ __nv_bfloat16 g_hb[NTOK*DIMD];          // conv out bf16 (expert L1 input)
__device__ float g_r1 [NTOK*DIMD];
__device__ float g_y  [NTOK*DIMD];
__device__ __nv_bfloat16 g_h1b[(size_t)NEXP*NTOK*INNERD];
__device__ __nv_bfloat16 g_h2b[(size_t)NEXP*NTOK*INNERD];
__device__ float g_eo [(size_t)NEXP*NTOK*DIMD];
__device__ int   g_cnt[NEXP];
__device__ int   g_idx[NEXP*NTOK];
__device__ int   g_tope[NTOK*2];
__device__ int   g_topp[NTOK*2];
__device__ float g_topw[NTOK*2];
__device__ float g_pp [NB*8*DIMD];
__device__ float g_gate[NB*DIMD];
// packed bf16 weights: [E][K/2][N] as uint32 (bf16 k-pair)
__device__ uint32_t g_wp1[(size_t)NEXP*(DIMD/2)*(2*INNERD)];
__device__ uint32_t g_wp2[(size_t)NEXP*(INNERD/2)*(2*INNERD)];
__device__ uint32_t g_wp3[(size_t)NEXP*(INNERD/2)*DIMD];

__device__ __forceinline__ float warp_sum(float v){
#pragma unroll
    for (int o = 16; o; o >>= 1) v += __shfl_xor_sync(0xffffffffu, v, o);
    return v;
}
__device__ __forceinline__ float siluf(float x){ return x / (1.f + expf(-x)); }

#define MMA_BF16(c0,c1,c2,c3,a0,a1,a2,a3,b0,b1) \
    asm volatile("mma.sync.aligned.m16n8k16.row.col.f32.bf16.bf16.f32 " \
        "{%0,%1,%2,%3}, {%4,%5,%6,%7}, {%8,%9}, {%0,%1,%2,%3};" \
        : "+f"(c0),"+f"(c1),"+f"(c2),"+f"(c3) \
        : "r"(a0),"r"(a1),"r"(a2),"r"(a3),"r"(b0),"r"(b1))

__device__ __forceinline__ void cpa16(uint32_t dst, const void* src, int sz){
    asm volatile("cp.async.cg.shared.global [%0], [%1], 16, %2;\n"
                 :: "r"(dst), "l"(src), "r"(sz));
}
__device__ __forceinline__ void cpa_commit(){ asm volatile("cp.async.commit_group;\n"); }
template<int N> __device__ __forceinline__ void cpa_wait(){
    asm volatile("cp.async.wait_group %0;\n" :: "n"(N));
}

// ---------------- weight pack: fp32 [E][K][N] -> bf16-pair uint32 [E][K/2][N] ----------------
__global__ void pack_k(const float* __restrict__ W, uint32_t* __restrict__ out,
                       int Kp, int N){
    size_t i = (size_t)blockIdx.x*256 + threadIdx.x;
    size_t total = (size_t)NEXP*Kp*N;
    if (i >= total) return;
    size_t n = i % N, ekp = i / N;
    size_t kp = ekp % Kp, e = ekp / Kp;
    const float* Wb = W + ((size_t)e*Kp*2 + kp*2)*N + n;
    __nv_bfloat162 v = __floats2bfloat162_rn(Wb[0], Wb[N]);
    out[i] = *(uint32_t*)&v;
}

// ---------------- LayerNorm ----------------
__global__ void ln_k(const float* __restrict__ res, const float* __restrict__ gg,
                     const float* __restrict__ bb){
    int n = blockIdx.x, tid = threadIdx.x;
    const float* r = res + (size_t)n*DIMD;
    float v0 = r[tid], v1 = r[tid+128], v2 = r[tid+256];
    __shared__ float redA[4], redB[4];
    int lane = tid & 31, wid = tid >> 5;
    float s = warp_sum(v0 + v1 + v2);
    if (lane == 0) redA[wid] = s;
    __syncthreads();
    float mu = (redA[0]+redA[1]+redA[2]+redA[3]) * (1.f/DIMD);
    float d0 = v0-mu, d1 = v1-mu, d2 = v2-mu;
    float q = warp_sum(d0*d0 + d1*d1 + d2*d2);
    if (lane == 0) redB[wid] = q;
    __syncthreads();
    float var = (redB[0]+redB[1]+redB[2]+redB[3]) * (1.f/DIMD);
    float inv = rsqrtf(var + 1e-5f);
    float* o = g_x + (size_t)n*DIMD;
    o[tid]     = d0*inv*gg[tid]     + bb[tid];
    o[tid+128] = d1*inv*gg[tid+128] + bb[tid+128];
    o[tid+256] = d2*inv*gg[tid+256] + bb[tid+256];
}

// ---------------- depthwise conv ----------------
__global__ void conv_k(const float* __restrict__ cw, const float* __restrict__ cb){
    int n = blockIdx.x, d = threadIdx.x;
    int b = n >> 10, t = n & 1023;
    float acc = cb[d];
    const float* wrow = cw + d*KSZ;
#pragma unroll
    for (int j = 0; j < KSZ; j++){
        int tt = t + j - 15;
        if (tt >= 0 && tt < TLEN)
            acc += g_x[((size_t)(b*TLEN + tt))*DIMD + d] * wrow[j];
    }
    g_h [(size_t)n*DIMD + d] = acc;
    g_hb[(size_t)n*DIMD + d] = __float2bfloat16(acc);
}

// ---------------- fp32 SIMT GEMM (router hidden) ----------------
#define BMr 64
#define BNr 64
#define BKr 16
__global__ __launch_bounds__(256) void gemm_r_k(
    const float* __restrict__ A, const float* __restrict__ W,
    const float* __restrict__ bias, float* __restrict__ C,
    int M, int Nn, int K)
{
    int bm = blockIdx.y * BMr, bn = blockIdx.x * BNr;
    __shared__ float As[BKr][BMr + 4];
    __shared__ float Bs[BKr][BNr];
    int tid = threadIdx.x;
    int arow = tid >> 2,  ak = (tid & 3)  << 2;
    int brow = tid >> 4,  bc = (tid & 15) << 2;
    int ty = tid >> 4,    tx = tid & 15;
    const float* Ap = A + (size_t)(bm + arow)*K;
    const float* Wp = W + (size_t)brow*Nn + bn + bc;
    float acc[4][4] = {};
    for (int kt = 0; kt < K; kt += BKr){
        float4 av = *(const float4*)(Ap + kt + ak);
        As[ak+0][arow] = av.x; As[ak+1][arow] = av.y;
        As[ak+2][arow] = av.z; As[ak+3][arow] = av.w;
        *(float4*)&Bs[brow][bc] = *(const float4*)(Wp + (size_t)kt*Nn);
        __syncthreads();
#pragma unroll
        for (int kk = 0; kk < BKr; kk++){
            float4 a = *(const float4*)&As[kk][ty << 2];
            float4 b = *(const float4*)&Bs[kk][tx << 2];
            acc[0][0] += a.x*b.x; acc[0][1] += a.x*b.y; acc[0][2] += a.x*b.z; acc[0][3] += a.x*b.w;
            acc[1][0] += a.y*b.x; acc[1][1] += a.y*b.y; acc[1][2] += a.y*b.z; acc[1][3] += a.y*b.w;
            acc[2][0] += a.z*b.x; acc[2][1] += a.z*b.y; acc[2][2] += a.z*b.z; acc[2][3] += a.z*b.w;
            acc[3][0] += a.w*b.x; acc[3][1] += a.w*b.y; acc[3][2] += a.w*b.z; acc[3][3] += a.w*b.w;
        }
        __syncthreads();
    }
#pragma unroll
    for (int i = 0; i < 4; i++){
#pragma unroll
        for (int j = 0; j < 4; j++){
            int cg = bn + (tx << 2) + j;
            float v = acc[i][j] + bias[cg];
            C[(size_t)(bm + (ty<<2) + i)*Nn + cg] = siluf(v);
        }
    }
}

// ---------------- bf16 tensor-core GEMM, cp.async double-buffered ----------------
// AMODE: 1 = gather A rows via g_idx (A = g_hb, [NTOK][K])
//        2 = per-expert compact rows   (A = bufs,  [E][NTOK][K])
// EPI:   2 = swiglu -> bf16 C [E][NTOK][nout]   (B covers both halves, BW=128)
//        3 = plain +bias -> fp32 g_eo [E][NTOK][nout]  (BW=64)
template<int AMODE, int EPI>
__global__ __launch_bounds__(256) void tgemm_k(
    const __nv_bfloat16* __restrict__ A, const uint32_t* __restrict__ Wp,
    const float* __restrict__ bias, __nv_bfloat16* __restrict__ C,
    float* __restrict__ Cf, int K, int Nw, int nout, int bias_len)
{
    constexpr int BW = (EPI == 2) ? 128 : 64;
    constexpr int BST = BW + 8;                       // stride ≡ 8 (mod 32): conflict-free
    constexpr int NH = (EPI == 2) ? 2 : 1;
    __shared__ uint32_t As[2][128][20];
    __shared__ uint32_t Bs[2][16][BST];

    int e = blockIdx.z;
    int cnt = g_cnt[e];
    int bm = blockIdx.y * 128;
    if (bm >= cnt) return;
    int bn = blockIdx.x * 64;

    const uint32_t* We = Wp + (size_t)e*(K/2)*Nw;
    const float*    be = bias + (size_t)e*bias_len;

    int tid = threadIdx.x, lane = tid & 31, wid = tid >> 5;
    int wm = wid & 3, wn = wid >> 2;
    int g = lane >> 2, tg = lane & 3;

    uint32_t s_as = (uint32_t)__cvta_generic_to_shared(&As[0][0][0]);
    uint32_t s_bs = (uint32_t)__cvta_generic_to_shared(&Bs[0][0][0]);

    // ---- A chunk sources (2 per thread: 512 chunks = 128 rows x 4x16B) ----
    const __nv_bfloat16* asrc[2]; int aok[2]; uint32_t adst[2];
#pragma unroll
    for (int u = 0; u < 2; u++){
        int c = tid + u*256;
        int r = c >> 2, off = c & 3;
        int rg = bm + r;
        int srow = (rg < cnt) ? ((AMODE == 1) ? g_idx[e*NTOK + rg] : rg) : -1;
        aok[u] = (srow >= 0) ? 16 : 0;
        size_t rowbase = 0;
        if (srow >= 0) rowbase = (AMODE == 1) ? (size_t)srow : ((size_t)e*NTOK + srow);
        asrc[u] = A + rowbase*K + off*8;
        adst[u] = s_as + (uint32_t)((r*20 + off*4)*4);
    }

    float acc[NH][2][4][4];
#pragma unroll
    for (int h = 0; h < NH; h++)
#pragma unroll
    for (int i = 0; i < 2; i++)
#pragma unroll
    for (int j = 0; j < 4; j++)
#pragma unroll
    for (int r = 0; r < 4; r++) acc[h][i][j][r] = 0.f;

    const int nt = K / 32;

    auto load_tile = [&](int kt, int buf){
        uint32_t abase = (uint32_t)(buf*128*20*4);
#pragma unroll
        for (int u = 0; u < 2; u++)
            cpa16(adst[u] + abase, asrc[u] + kt, aok[u]);
        uint32_t bbase = (uint32_t)(buf*16*BST*4);
        if (EPI == 2){
#pragma unroll
            for (int u = 0; u < 2; u++){
                int c = tid + u*256;
                int r = c >> 5, cc = c & 31;
                int col = (cc < 16) ? (bn + cc*4) : (INNERD + bn + (cc-16)*4);
                uint32_t dst = s_bs + bbase + (uint32_t)((r*BST + cc*4)*4);
                cpa16(dst, We + (size_t)(kt/2 + r)*Nw + col, 16);
            }
        } else {
            int r = tid >> 4, cc = tid & 15;
            int col = bn + cc*4;
            uint32_t dst = s_bs + bbase + (uint32_t)((r*BST + cc*4)*4);
            cpa16(dst, We + (size_t)(kt/2 + r)*Nw + col, 16);
        }
        cpa_commit();
    };

    load_tile(0, 0);
    for (int t = 0; t < nt; t++){
        int buf = t & 1;
        if (t + 1 < nt){ load_tile((t+1)*32, buf ^ 1); cpa_wait<1>(); }
        else            cpa_wait<0>();
        __syncthreads();

#pragma unroll
        for (int kk = 0; kk < 2; kk++){
            uint32_t a[2][4];
#pragma unroll
            for (int i = 0; i < 2; i++){
                int r0 = wm*32 + i*16;
                a[i][0] = As[buf][r0+g   ][kk*8+tg  ];
                a[i][1] = As[buf][r0+g+8 ][kk*8+tg  ];
                a[i][2] = As[buf][r0+g   ][kk*8+tg+4];
                a[i][3] = As[buf][r0+g+8 ][kk*8+tg+4];
            }
#pragma unroll
            for (int h = 0; h < NH; h++){
#pragma unroll
                for (int j = 0; j < 4; j++){
                    int c0 = h*64 + wn*32 + j*8 + g;
                    uint32_t b0 = Bs[buf][kk*8+tg  ][c0];
                    uint32_t b1 = Bs[buf][kk*8+tg+4][c0];
#pragma unroll
                    for (int i = 0; i < 2; i++)
                        MMA_BF16(acc[h][i][j][0], acc[h][i][j][1],
                                 acc[h][i][j][2], acc[h][i][j][3],
                                 a[i][0], a[i][1], a[i][2], a[i][3], b0, b1);
                }
            }
        }
        __syncthreads();
    }

    // ---- epilogue ----
#pragma unroll
    for (int i = 0; i < 2; i++){
        int rA = bm + wm*32 + i*16 + g;
        int rB = rA + 8;
#pragma unroll
        for (int j = 0; j < 4; j++){
            int col = bn + wn*32 + j*8 + 2*tg;
            if (EPI == 2){
                float ba0 = be[col],        ba1 = be[col+1];
                float bg0 = be[INNERD+col], bg1 = be[INNERD+col+1];
                if (rA < cnt){
                    float v0 = (acc[0][i][j][0]+ba0)*siluf(acc[1][i][j][0]+bg0);
                    float v1 = (acc[0][i][j][1]+ba1)*siluf(acc[1][i][j][1]+bg1);
                    *(__nv_bfloat162*)(C + ((size_t)e*NTOK + rA)*nout + col)
                        = __floats2bfloat162_rn(v0, v1);
                }
                if (rB < cnt){
                    float v0 = (acc[0][i][j][2]+ba0)*siluf(acc[1][i][j][2]+bg0);
                    float v1 = (acc[0][i][j][3]+ba1)*siluf(acc[1][i][j][3]+bg1);
                    *(__nv_bfloat162*)(C + ((size_t)e*NTOK + rB)*nout + col)
                        = __floats2bfloat162_rn(v0, v1);
                }
            } else {
                float b0 = be[col], b1 = be[col+1];
                if (rA < cnt){
                    float2 v = make_float2(acc[0][i][j][0]+b0, acc[0][i][j][1]+b1);
                    *(float2*)(Cf + ((size_t)e*NTOK + rA)*nout + col) = v;
                }
                if (rB < cnt){
                    float2 v = make_float2(acc[0][i][j][2]+b0, acc[0][i][j][3]+b1);
                    *(float2*)(Cf + ((size_t)e*NTOK + rB)*nout + col) = v;
                }
            }
        }
    }
}

// ---------------- router top-2 ----------------
__global__ void zero_k(){ if (threadIdx.x < NEXP) g_cnt[threadIdx.x] = 0; }

__global__ void route_k(const float* __restrict__ rw2, const float* __restrict__ rb2){
    int gt = blockIdx.x*blockDim.x + threadIdx.x;
    int n = gt >> 5, lane = gt & 31;
    if (n >= NTOK) return;
    const float* row = g_r1 + (size_t)n*DIMD;
    float a0=0,a1=0,a2=0,a3=0,a4=0;
    for (int d = lane; d < DIMD; d += 32){
        float v = row[d];
        const float* w = rw2 + d*NEXP;
        a0 += v*w[0]; a1 += v*w[1]; a2 += v*w[2]; a3 += v*w[3]; a4 += v*w[4];
    }
    a0=warp_sum(a0); a1=warp_sum(a1); a2=warp_sum(a2); a3=warp_sum(a3); a4=warp_sum(a4);
    if (lane == 0){
        float v[NEXP] = {a0+rb2[0], a1+rb2[1], a2+rb2[2], a3+rb2[3], a4+rb2[4]};
        int e0 = 0;
        for (int e = 1; e < NEXP; e++) if (v[e] > v[e0]) e0 = e;
        int e1 = -1;
        for (int e = 0; e < NEXP; e++){ if (e == e0) continue; if (e1 < 0 || v[e] > v[e1]) e1 = e; }
        float ex = expf(v[e1] - v[e0]);
        float w0 = 1.f/(1.f+ex), w1 = ex/(1.f+ex);
        int p0 = atomicAdd(&g_cnt[e0], 1); g_idx[e0*NTOK+p0] = n;
        int p1 = atomicAdd(&g_cnt[e1], 1); g_idx[e1*NTOK+p1] = n;
        g_tope[2*n] = e0; g_topp[2*n] = p0; g_topw[2*n] = w0;
        g_tope[2*n+1] = e1; g_topp[2*n+1] = p1; g_topw[2*n+1] = w1;
    }
}

// ---------------- combine: y = tok + w0*eo0 + w1*eo1 (deterministic) ----------------
__global__ void combine_k(){
    int i = blockIdx.x*256 + threadIdx.x;
    if (i >= NTOK*DIMD) return;
    int n = i / DIMD, d = i - n*DIMD;
    int e0 = g_tope[2*n], p0 = g_topp[2*n];
    int e1 = g_tope[2*n+1], p1 = g_topp[2*n+1];
    float v = g_h[i]
            + g_topw[2*n]  * g_eo[((size_t)e0*NTOK + p0)*DIMD + d]
            + g_topw[2*n+1]* g_eo[((size_t)e1*NTOK + p1)*DIMD + d];
    g_y[i] = v;
}

// ---------------- senet ----------------
__global__ void pool_k(const float* __restrict__ senet){
    int tc = blockIdx.x, dc = blockIdx.y, b = blockIdx.z, tid = threadIdx.x;
    int d = dc*128 + tid;
    float sr = senet[d];
    float acc = 0.f;
    int base = b*TLEN + tc*128;
    for (int t = 0; t < 128; t++){
        size_t nn = (size_t)(base + t)*DIMD + d;
        acc += g_x[nn]*sr + g_y[nn];
    }
    g_pp[(b*8 + tc)*DIMD + d] = acc;
}

__global__ void gate_k(const float* __restrict__ sw1, const float* __restrict__ sb1,
                       const float* __restrict__ sw2, const float* __restrict__ sb2){
    int b = blockIdx.x, tid = threadIdx.x;
    __shared__ float pooled[DIMD];
    __shared__ float s1[48];
    float s = 0.f;
    for (int ch = 0; ch < 8; ch++) s += g_pp[(b*8 + ch)*DIMD + tid];
    pooled[tid] = s * (1.f/1024.f);
    __syncthreads();
    if (tid < 48){
        float acc = sb1[tid];
        for (int d = 0; d < DIMD; d++) acc += pooled[d]*sw1[d*48 + tid];
        s1[tid] = siluf(acc);
    }
    __syncthreads();
    float acc = sb2[tid];
    for (int q = 0; q < 48; q++) acc += s1[q]*sw2[q*DIMD + tid];
    g_gate[b*DIMD + tid] = 1.f/(1.f + expf(-acc));
}

__global__ void final_k(const float* __restrict__ res, float* __restrict__ out){
    int i = blockIdx.x*256 + threadIdx.x;
    if (i >= NTOK*DIMD) return;
    int d = i % DIMD;
    int b = i / (TLEN*DIMD);
    out[i] = res[i] + g_y[i]*g_gate[b*DIMD + d];
}

// =============================== launch ===============================
extern "C" void kernel_launch(void* const* d_in, const int* in_sizes, int n_in,
                              void* d_out, int out_size){
    const float* res    = (const float*)d_in[0];
    const float* ln_g   = (const float*)d_in[1];
    const float* ln_b   = (const float*)d_in[2];
    const float* conv_w = (const float*)d_in[3];
    const float* conv_b = (const float*)d_in[4];
    const float* rw1    = (const float*)d_in[5];
    const float* rb1    = (const float*)d_in[6];
    const float* rw2    = (const float*)d_in[7];
    const float* rb2    = (const float*)d_in[8];
    const float* we1    = (const float*)d_in[9];
    const float* be1    = (const float*)d_in[10];
    const float* we2    = (const float*)d_in[11];
    const float* be2    = (const float*)d_in[12];
    const float* we3    = (const float*)d_in[13];
    const float* be3    = (const float*)d_in[14];
    const float* sw1    = (const float*)d_in[15];
    const float* sb1    = (const float*)d_in[16];
    const float* sw2    = (const float*)d_in[17];
    const float* sb2    = (const float*)d_in[18];
    const float* senet  = (const float*)d_in[19];
    float* out = (float*)d_out;

    float *ph, *pr1;
    __nv_bfloat16 *phb, *ph1b, *ph2b;
    float *peo;
    uint32_t *pw1, *pw2, *pw3;
    cudaGetSymbolAddress((void**)&ph,   g_h);
    cudaGetSymbolAddress((void**)&phb,  g_hb);
    cudaGetSymbolAddress((void**)&pr1,  g_r1);
    cudaGetSymbolAddress((void**)&ph1b, g_h1b);
    cudaGetSymbolAddress((void**)&ph2b, g_h2b);
    cudaGetSymbolAddress((void**)&peo,  g_eo);
    cudaGetSymbolAddress((void**)&pw1,  g_wp1);
    cudaGetSymbolAddress((void**)&pw2,  g_wp2);
    cudaGetSymbolAddress((void**)&pw3,  g_wp3);

    // weight packing (independent of activations)
    {
        size_t t1 = (size_t)NEXP*(DIMD/2)*(2*INNERD);
        size_t t2 = (size_t)NEXP*(INNERD/2)*(2*INNERD);
        size_t t3 = (size_t)NEXP*(INNERD/2)*DIMD;
        pack_k<<<(unsigned)((t1+255)/256), 256>>>(we1, pw1, DIMD/2,   2*INNERD);
        pack_k<<<(unsigned)((t2+255)/256), 256>>>(we2, pw2, INNERD/2, 2*INNERD);
        pack_k<<<(unsigned)((t3+255)/256), 256>>>(we3, pw3, INNERD/2, DIMD);
    }

    ln_k  <<<NTOK, 128>>>(res, ln_g, ln_b);
    conv_k<<<NTOK, DIMD>>>(conv_w, conv_b);

    gemm_r_k<<<dim3(DIMD/BNr, NTOK/BMr), 256>>>(ph, rw1, rb1, pr1, NTOK, DIMD, DIMD);
    zero_k <<<1, 32>>>();
    route_k<<<NTOK/8, 256>>>(rw2, rb2);

    // expert layers — all experts in one launch per layer
    tgemm_k<1,2><<<dim3(INNERD/64, NTOK/128, NEXP), 256>>>(
        phb,  pw1, be1, ph1b, nullptr, DIMD,   2*INNERD, INNERD, 2*INNERD);
    tgemm_k<2,2><<<dim3(INNERD/64, NTOK/128, NEXP), 256>>>(
        ph1b, pw2, be2, ph2b, nullptr, INNERD, 2*INNERD, INNERD, 2*INNERD);
    tgemm_k<2,3><<<dim3(DIMD/64,   NTOK/128, NEXP), 256>>>(
        ph2b, pw3, be3, nullptr, peo,  INNERD, DIMD,     DIMD,   DIMD);

    combine_k<<<(NTOK*DIMD + 255)/256, 256>>>();
    pool_k <<<dim3(8, 3, NB), 128>>>(senet);
    gate_k <<<NB, DIMD>>>(sw1, sb1, sw2, sb2);
    final_k<<<(NTOK*DIMD + 255)/256, 256>>>(res, out);
}